// round 1
// baseline (speedup 1.0000x reference)
#include <cuda_runtime.h>
#include <math.h>

#define BB   8
#define CIN  64
#define COUT 64
#define HH   128
#define WW   128
#define KK   9
#define HW   (HH*WW)

// ---------------- scratch (device globals; no allocations) ----------------
__device__ float g_off [BB*18*HW];        // 9.4 MB
__device__ float g_mask[BB*9*HW];         // 4.7 MB
__device__ float g_y   [BB*COUT*HW];      // 33.5 MB
__device__ float g_wt  [KK*CIN*COUT];     // transposed main weights [k][c][oc]
__device__ float g_sum [COUT];
__device__ float g_sumsq[COUT];

// ---------------- kernel T: transpose main conv weights ----------------
__global__ void k_transpose(const float* __restrict__ w) {
    int i = blockIdx.x * 256 + threadIdx.x;
    if (i >= KK*CIN*COUT) return;
    int oc = i % COUT;
    int c  = (i / COUT) % CIN;
    int k  = i / (COUT*CIN);
    g_wt[i] = w[(oc*CIN + c)*KK + k];
}

// ---------------- kernel A: offset(18) + mask(9) 3x3 conv ----------------
__global__ __launch_bounds__(256) void k_offmask(
    const float* __restrict__ x,
    const float* __restrict__ ow, const float* __restrict__ ob,
    const float* __restrict__ mw, const float* __restrict__ mb)
{
    extern __shared__ float wsh[];   // [27][64][12] padded, 82944 B
    int tid = threadIdx.x;

    // zero BN accumulators once per launch (stream-ordered before k_reduce)
    if (blockIdx.x == 0 && tid < 2*COUT) {
        if (tid < COUT) g_sum[tid] = 0.f; else g_sumsq[tid-COUT] = 0.f;
    }

    // stage combined weights: oc<18 -> offset conv, oc>=18 -> mask conv
    for (int i = tid; i < 27*CIN*KK; i += 256) {
        int j  = i % KK;
        int c  = (i / KK) % CIN;
        int oc = i / (KK*CIN);
        float v = (oc < 18) ? ow[(oc*CIN + c)*KK + j]
                            : mw[((oc-18)*CIN + c)*KK + j];
        wsh[(oc*CIN + c)*12 + j] = v;
    }
    __syncthreads();

    int b  = blockIdx.x / (HH/2);
    int h  = (blockIdx.x % (HH/2))*2 + (tid >> 7);
    int wc = tid & 127;

    float acc[27];
#pragma unroll
    for (int o = 0; o < 18; o++) acc[o] = ob[o];
#pragma unroll
    for (int o = 0; o < 9;  o++) acc[18+o] = mb[o];

    const float* xb = x + (size_t)(b*CIN)*HW + h*WW + wc;
    bool hu = (h > 0), hd = (h < HH-1), wl = (wc > 0), wr = (wc < WW-1);

    for (int c = 0; c < CIN; c++) {
        const float* xc = xb + c*HW;
        float xv[9];
        xv[0] = (hu&&wl) ? xc[-WW-1] : 0.f;
        xv[1] =  hu      ? xc[-WW  ] : 0.f;
        xv[2] = (hu&&wr) ? xc[-WW+1] : 0.f;
        xv[3] =  wl      ? xc[-1   ] : 0.f;
        xv[4] =            xc[0];
        xv[5] =  wr      ? xc[ 1   ] : 0.f;
        xv[6] = (hd&&wl) ? xc[ WW-1] : 0.f;
        xv[7] =  hd      ? xc[ WW  ] : 0.f;
        xv[8] = (hd&&wr) ? xc[ WW+1] : 0.f;
#pragma unroll
        for (int o = 0; o < 27; o++) {
            const float* wr_ = &wsh[(o*CIN + c)*12];
            float a = acc[o];
#pragma unroll
            for (int j = 0; j < 9; j++) a += xv[j]*wr_[j];
            acc[o] = a;
        }
    }

    int pix = h*WW + wc;
#pragma unroll
    for (int o = 0; o < 18; o++)
        g_off[(b*18 + o)*HW + pix] = acc[o];
#pragma unroll
    for (int o = 0; o < 9; o++)
        g_mask[(b*9 + o)*HW + pix] = 2.0f / (1.0f + __expf(-acc[18+o]));
}

// ---------------- kernel B: deformable conv (sample + GEMM per k) ----------------
__global__ __launch_bounds__(256) void k_deform(
    const float* __restrict__ x, const float* __restrict__ bias)
{
    __shared__ int   s_idx[KK][32][4];
    __shared__ float s_w  [KK][32][4];
    __shared__ float s_wk [CIN*COUT];   // [c][oc] per-k slice; reused as [oc][33] out buf
    __shared__ float s_s  [32][68];     // [pixel][c] samples (pad 68 keeps 16B align)

    int tid = threadIdx.x;
    int b = blockIdx.z, h = blockIdx.y, w0 = blockIdx.x * 32;

    // phase 0: per (k, pixel) bilinear coords, clipped indices + fused weights*mask
    for (int i = tid; i < KK*32; i += 256) {
        int k = i >> 5, p = i & 31;
        int wc = w0 + p;
        float dy = g_off[((b*18 + 2*k  )*HH + h)*WW + wc];
        float dx = g_off[((b*18 + 2*k+1)*HH + h)*WW + wc];
        float m  = g_mask[((b*9 + k)*HH + h)*WW + wc];
        float py = dy + (float)(k/3 - 1) + (float)h;
        float px = dx + (float)(k%3 - 1) + (float)wc;
        float y0f = floorf(py), x0f = floorf(px);
        float ly = py - y0f, lx = px - x0f;
        int y0 = (int)y0f, x0i = (int)x0f;
        int y1 = y0 + 1,   x1 = x0i + 1;
        bool vy0 = (y0  >= 0 && y0  < HH), vy1 = (y1 >= 0 && y1 < HH);
        bool vx0 = (x0i >= 0 && x0i < WW), vx1 = (x1 >= 0 && x1 < WW);
        int yc0 = min(max(y0 ,0),HH-1), yc1 = min(max(y1,0),HH-1);
        int xc0 = min(max(x0i,0),WW-1), xc1 = min(max(x1,0),WW-1);
        s_idx[k][p][0] = yc0*WW + xc0;
        s_idx[k][p][1] = yc0*WW + xc1;
        s_idx[k][p][2] = yc1*WW + xc0;
        s_idx[k][p][3] = yc1*WW + xc1;
        s_w[k][p][0] = (vy0&&vx0) ? (1.f-ly)*(1.f-lx)*m : 0.f;
        s_w[k][p][1] = (vy0&&vx1) ? (1.f-ly)*lx*m       : 0.f;
        s_w[k][p][2] = (vy1&&vx0) ? ly*(1.f-lx)*m       : 0.f;
        s_w[k][p][3] = (vy1&&vx1) ? ly*lx*m             : 0.f;
    }

    float acc[8];
#pragma unroll
    for (int i = 0; i < 8; i++) acc[i] = 0.f;

    int oc = tid & 63, pg = tid >> 6;        // GEMM mapping: 1 oc x 8 pixels
    int wid = tid >> 5, lane = tid & 31;     // sampling: warp = 8 channels, lane = pixel
    const float* xb = x + (size_t)b*CIN*HW;

    for (int k = 0; k < KK; k++) {
        __syncthreads();  // protects s_wk & s_s reuse; covers phase-0 for k=0
        // stage w_k [c][oc] (contiguous 16 KB from transposed weights)
        for (int i = tid; i < CIN*COUT; i += 256)
            s_wk[i] = g_wt[k*CIN*COUT + i];

        // sampling: lane = pixel, warp covers 8 channels
        int p = lane;
        int   i00 = s_idx[k][p][0], i01 = s_idx[k][p][1];
        int   i10 = s_idx[k][p][2], i11 = s_idx[k][p][3];
        float W00 = s_w[k][p][0], W01 = s_w[k][p][1];
        float W10 = s_w[k][p][2], W11 = s_w[k][p][3];
#pragma unroll
        for (int ci = 0; ci < 8; ci++) {
            int c = wid*8 + ci;
            const float* xc = xb + c*HW;
            s_s[p][c] = xc[i00]*W00 + xc[i01]*W01 + xc[i10]*W10 + xc[i11]*W11;
        }
        __syncthreads();

        // GEMM partial: acc[p] += s[p][c] * wk[c][oc]
#pragma unroll
        for (int c = 0; c < CIN; c += 4) {
            float w0 = s_wk[(c  )*COUT + oc];
            float w1 = s_wk[(c+1)*COUT + oc];
            float w2 = s_wk[(c+2)*COUT + oc];
            float w3 = s_wk[(c+3)*COUT + oc];
#pragma unroll
            for (int i = 0; i < 8; i++) {
                float4 s4 = *(const float4*)&s_s[pg*8 + i][c];
                acc[i] += s4.x*w0 + s4.y*w1 + s4.z*w2 + s4.w*w3;
            }
        }
    }

    // write out via smem transpose -> coalesced STG
    __syncthreads();
    float bo = bias[oc];
#pragma unroll
    for (int i = 0; i < 8; i++)
        s_wk[oc*33 + pg*8 + i] = acc[i] + bo;
    __syncthreads();
    for (int i = tid; i < COUT*32; i += 256) {
        int o = i >> 5, p = i & 31;
        g_y[((size_t)b*COUT + o)*HW + h*WW + w0 + p] = s_wk[o*33 + p];
    }
}

// ---------------- kernel C: per-channel sum / sumsq ----------------
__global__ __launch_bounds__(256) void k_reduce() {
    int plane = blockIdx.x;              // b*64 + c, matches g_y layout
    int c = plane & 63;
    const float4* yp = (const float4*)(g_y + (size_t)plane * HW);
    float s = 0.f, sq = 0.f;
    for (int i = threadIdx.x; i < HW/4; i += 256) {
        float4 v = yp[i];
        s  += v.x + v.y + v.z + v.w;
        sq += v.x*v.x + v.y*v.y + v.z*v.z + v.w*v.w;
    }
#pragma unroll
    for (int o = 16; o > 0; o >>= 1) {
        s  += __shfl_down_sync(0xffffffffu, s,  o);
        sq += __shfl_down_sync(0xffffffffu, sq, o);
    }
    __shared__ float ss[8], ssq[8];
    if ((threadIdx.x & 31) == 0) { ss[threadIdx.x>>5] = s; ssq[threadIdx.x>>5] = sq; }
    __syncthreads();
    if (threadIdx.x == 0) {
        float t = 0.f, tq = 0.f;
#pragma unroll
        for (int i = 0; i < 8; i++) { t += ss[i]; tq += ssq[i]; }
        atomicAdd(&g_sum[c], t);
        atomicAdd(&g_sumsq[c], tq);
    }
}

// ---------------- kernel D: batchnorm + relu ----------------
__global__ __launch_bounds__(256) void k_bn(
    const float* __restrict__ gamma, const float* __restrict__ beta,
    float* __restrict__ out)
{
    int i4 = blockIdx.x * 256 + threadIdx.x;      // element/4 index
    if (i4 >= BB*COUT*HW/4) return;
    int c = (i4 >> 12) & 63;                      // (i4*4 / 16384) % 64
    const float N = (float)(BB*HW);
    float mean = g_sum[c] / N;
    float var  = g_sumsq[c]/N - mean*mean;
    float inv  = rsqrtf(var + 1e-5f);
    float sc   = gamma[c]*inv;
    float sh   = beta[c] - mean*sc;
    float4 v = ((const float4*)g_y)[i4];
    float4 r;
    r.x = fmaxf(v.x*sc + sh, 0.f);
    r.y = fmaxf(v.y*sc + sh, 0.f);
    r.z = fmaxf(v.z*sc + sh, 0.f);
    r.w = fmaxf(v.w*sc + sh, 0.f);
    ((float4*)out)[i4] = r;
}

// ---------------- launch ----------------
extern "C" void kernel_launch(void* const* d_in, const int* in_sizes, int n_in,
                              void* d_out, int out_size)
{
    const float* x     = (const float*)d_in[0];
    const float* ow    = (const float*)d_in[1];
    const float* ob    = (const float*)d_in[2];
    const float* mw    = (const float*)d_in[3];
    const float* mb    = (const float*)d_in[4];
    const float* w     = (const float*)d_in[5];
    const float* bias  = (const float*)d_in[6];
    const float* gamma = (const float*)d_in[7];
    const float* beta  = (const float*)d_in[8];

    const int smemA = 27*CIN*12*4;   // 82944 B dynamic smem for k_offmask
    cudaFuncSetAttribute(k_offmask, cudaFuncAttributeMaxDynamicSharedMemorySize, smemA);

    k_transpose<<<(KK*CIN*COUT + 255)/256, 256>>>(w);
    k_offmask<<<BB*HH/2, 256, smemA>>>(x, ow, ob, mw, mb);
    dim3 gb(WW/32, HH, BB);
    k_deform<<<gb, 256>>>(x, bias);
    k_reduce<<<BB*COUT, 256>>>();
    k_bn<<<(BB*COUT*HW/4 + 255)/256, 256>>>(gamma, beta, (float*)d_out);
}

// round 2
// speedup vs baseline: 1.3602x; 1.3602x over previous
#include <cuda_runtime.h>
#include <math.h>

#define BB   8
#define CIN  64
#define COUT 64
#define HH   128
#define WW   128
#define KK   9
#define HW   (HH*WW)

// ---------------- scratch (device globals; no allocations) ----------------
__device__ float g_off [BB*18*HW];
__device__ float g_mask[BB*9*HW];
__device__ float g_y   [BB*COUT*HW];
__device__ float g_wt  [KK*CIN*COUT];     // transposed main weights [k][c][oc]
__device__ float g_sum [COUT];
__device__ float g_sumsq[COUT];

// ---------------- kernel T: transpose main conv weights + zero BN accumulators ----------------
__global__ void k_transpose(const float* __restrict__ w) {
    int i = blockIdx.x * 256 + threadIdx.x;
    if (blockIdx.x == 0 && threadIdx.x < 2*COUT) {
        if (threadIdx.x < COUT) g_sum[threadIdx.x] = 0.f;
        else                    g_sumsq[threadIdx.x - COUT] = 0.f;
    }
    if (i >= KK*CIN*COUT) return;
    int oc = i % COUT;
    int c  = (i / COUT) % CIN;
    int k  = i / (COUT*CIN);
    g_wt[i] = w[(oc*CIN + c)*KK + k];
}

// ---------------- kernel A: offset(18) + mask(9) 3x3 conv ----------------
// Block: 256 threads, 4 rows of the image. Each thread owns 2 vertically
// adjacent pixels -> shares the 81 weight LDS and 6/12 of the x taps.
__global__ __launch_bounds__(256) void k_offmask(
    const float* __restrict__ x,
    const float* __restrict__ ow, const float* __restrict__ ob,
    const float* __restrict__ mw, const float* __restrict__ mb)
{
    extern __shared__ float wsh[];   // [27][64][12] padded, 82944 B
    int tid = threadIdx.x;

    // stage combined weights: oc<18 -> offset conv, oc>=18 -> mask conv
    for (int i = tid; i < 27*CIN*KK; i += 256) {
        int j  = i % KK;
        int c  = (i / KK) % CIN;
        int oc = i / (KK*CIN);
        float v = (oc < 18) ? ow[(oc*CIN + c)*KK + j]
                            : mw[((oc-18)*CIN + c)*KK + j];
        wsh[(oc*CIN + c)*12 + j] = v;
    }
    __syncthreads();

    int b     = blockIdx.x / (HH/4);
    int hbase = (blockIdx.x % (HH/4)) * 4;
    int h0    = hbase + (tid >> 7) * 2;     // this thread: rows h0, h0+1
    int wc    = tid & 127;

    float acc[2][27];
#pragma unroll
    for (int o = 0; o < 18; o++) { float v = ob[o]; acc[0][o] = v; acc[1][o] = v; }
#pragma unroll
    for (int o = 0; o < 9;  o++) { float v = mb[o]; acc[0][18+o] = v; acc[1][18+o] = v; }

    const float* xb = x + (size_t)(b*CIN)*HW + h0*WW + wc;
    bool wl = (wc > 0), wr = (wc < WW-1);
    bool rv0 = (h0 > 0), rv3 = (h0 + 2 < HH);   // rows h0-1 / h0+2

    for (int c = 0; c < CIN; c++) {
        const float* xc = xb + c*HW;
        float xa[4][3];   // rows h0-1 .. h0+2, cols wc-1..wc+1
        xa[0][0] = (rv0 && wl) ? xc[-WW-1] : 0.f;
        xa[0][1] =  rv0        ? xc[-WW  ] : 0.f;
        xa[0][2] = (rv0 && wr) ? xc[-WW+1] : 0.f;
        xa[1][0] =  wl ? xc[-1] : 0.f;
        xa[1][1] =       xc[0];
        xa[1][2] =  wr ? xc[ 1] : 0.f;
        xa[2][0] =  wl ? xc[WW-1] : 0.f;
        xa[2][1] =       xc[WW  ];
        xa[2][2] =  wr ? xc[WW+1] : 0.f;
        xa[3][0] = (rv3 && wl) ? xc[2*WW-1] : 0.f;
        xa[3][1] =  rv3        ? xc[2*WW  ] : 0.f;
        xa[3][2] = (rv3 && wr) ? xc[2*WW+1] : 0.f;

#pragma unroll
        for (int o = 0; o < 27; o++) {
            const float4* wp = (const float4*)&wsh[(o*CIN + c)*12];
            float4 wA = wp[0];                 // j0..3
            float4 wB = wp[1];                 // j4..7
            float  w8 = wsh[(o*CIN + c)*12 + 8];
            acc[0][o] += xa[0][0]*wA.x + xa[0][1]*wA.y + xa[0][2]*wA.z
                       + xa[1][0]*wA.w + xa[1][1]*wB.x + xa[1][2]*wB.y
                       + xa[2][0]*wB.z + xa[2][1]*wB.w + xa[2][2]*w8;
            acc[1][o] += xa[1][0]*wA.x + xa[1][1]*wA.y + xa[1][2]*wA.z
                       + xa[2][0]*wA.w + xa[2][1]*wB.x + xa[2][2]*wB.y
                       + xa[3][0]*wB.z + xa[3][1]*wB.w + xa[3][2]*w8;
        }
    }

#pragma unroll
    for (int r = 0; r < 2; r++) {
        int pix = (h0 + r)*WW + wc;
#pragma unroll
        for (int o = 0; o < 18; o++)
            g_off[(b*18 + o)*HW + pix] = acc[r][o];
#pragma unroll
        for (int o = 0; o < 9; o++)
            g_mask[(b*9 + o)*HW + pix] = 2.0f / (1.0f + __expf(-acc[r][18+o]));
    }
}

// ---------------- kernel B: deformable conv + fused BN reduction ----------------
// Block: 256 threads, tile = 64 pixels x 64 oc. Thread = 4 oc x 4 px.
// Dynamic smem partition (52224 B):
//   [0,16384)       s_wk  [c][oc] per-k weight slice
//   [16384,33792)   s_s   [64 px][68] samples   (reused as s_out [64 oc][67])
//   [33792,43008)   s_idx [9][64][4] clipped indices (reused as s_red)
//   [43008,52224)   s_w   [9][64][4] bilinear*mask weights (reused as s_red2)
__global__ __launch_bounds__(256) void k_deform(
    const float* __restrict__ x, const float* __restrict__ bias)
{
    extern __shared__ float smem[];
    float* s_wk  = smem;                    // 4096 floats
    float* s_s   = smem + 4096;             // 64*68 floats
    int*   s_idx = (int*)(smem + 4096 + 64*68);       // 9*64*4
    float* s_w   = smem + 4096 + 64*68 + 9*64*4;      // 9*64*4

    int tid = threadIdx.x;
    int b = blockIdx.z, h = blockIdx.y, w0 = blockIdx.x * 64;

    // phase 0: per (k, pixel) clipped indices + fused bilinear*mask weights
    for (int i = tid; i < KK*64; i += 256) {
        int k = i >> 6, p = i & 63;
        int wc = w0 + p;
        float dy = g_off[((b*18 + 2*k  )*HH + h)*WW + wc];
        float dx = g_off[((b*18 + 2*k+1)*HH + h)*WW + wc];
        float m  = g_mask[((b*9 + k)*HH + h)*WW + wc];
        float py = dy + (float)(k/3 - 1) + (float)h;
        float px = dx + (float)(k%3 - 1) + (float)wc;
        float y0f = floorf(py), x0f = floorf(px);
        float ly = py - y0f, lx = px - x0f;
        int y0 = (int)y0f, x0i = (int)x0f;
        int y1 = y0 + 1,   x1 = x0i + 1;
        bool vy0 = (y0  >= 0 && y0  < HH), vy1 = (y1 >= 0 && y1 < HH);
        bool vx0 = (x0i >= 0 && x0i < WW), vx1 = (x1 >= 0 && x1 < WW);
        int yc0 = min(max(y0 ,0),HH-1), yc1 = min(max(y1,0),HH-1);
        int xc0 = min(max(x0i,0),WW-1), xc1 = min(max(x1,0),WW-1);
        s_idx[(k*64 + p)*4 + 0] = yc0*WW + xc0;
        s_idx[(k*64 + p)*4 + 1] = yc0*WW + xc1;
        s_idx[(k*64 + p)*4 + 2] = yc1*WW + xc0;
        s_idx[(k*64 + p)*4 + 3] = yc1*WW + xc1;
        s_w[(k*64 + p)*4 + 0] = (vy0&&vx0) ? (1.f-ly)*(1.f-lx)*m : 0.f;
        s_w[(k*64 + p)*4 + 1] = (vy0&&vx1) ? (1.f-ly)*lx*m       : 0.f;
        s_w[(k*64 + p)*4 + 2] = (vy1&&vx0) ? ly*(1.f-lx)*m       : 0.f;
        s_w[(k*64 + p)*4 + 3] = (vy1&&vx1) ? ly*lx*m             : 0.f;
    }

    float acc[4][4];   // [px][oc]
#pragma unroll
    for (int i = 0; i < 4; i++)
#pragma unroll
        for (int j = 0; j < 4; j++) acc[i][j] = 0.f;

    int ocg = (tid & 15) * 4;      // oc group (4 consecutive oc)
    int pgb = (tid >> 4) * 4;      // pixel group (4 consecutive px)
    int ps  = tid & 63;            // sampling: pixel
    int csb = tid >> 6;            // sampling: channel stride base (0..3)
    const float* xb = x + (size_t)b*CIN*HW;

#pragma unroll 1
    for (int k = 0; k < KK; k++) {
        __syncthreads();  // previous GEMM done; safe to overwrite s_wk/s_s
        // stage w_k [c][oc] (16 KB contiguous)
        {
            const float4* src = (const float4*)(g_wt + k*CIN*COUT);
            float4* dst = (float4*)s_wk;
            for (int i = tid; i < CIN*COUT/4; i += 256) dst[i] = src[i];
        }
        // sampling: lane group = pixel, each thread covers 16 channels
        {
            int i00 = s_idx[(k*64 + ps)*4 + 0], i01 = s_idx[(k*64 + ps)*4 + 1];
            int i10 = s_idx[(k*64 + ps)*4 + 2], i11 = s_idx[(k*64 + ps)*4 + 3];
            float W00 = s_w[(k*64 + ps)*4 + 0], W01 = s_w[(k*64 + ps)*4 + 1];
            float W10 = s_w[(k*64 + ps)*4 + 2], W11 = s_w[(k*64 + ps)*4 + 3];
#pragma unroll 4
            for (int ci = 0; ci < 16; ci++) {
                int c = csb + ci*4;
                const float* xc = xb + c*HW;
                s_s[ps*68 + c] = xc[i00]*W00 + xc[i01]*W01 + xc[i10]*W10 + xc[i11]*W11;
            }
        }
        __syncthreads();

        // GEMM partial: acc[p][o] += s[p][c] * wk[c][o]
#pragma unroll 4
        for (int c = 0; c < CIN; c += 4) {
            float wv[4][4];   // [dc][oc]
            *(float4*)wv[0] = *(const float4*)&s_wk[(c+0)*COUT + ocg];
            *(float4*)wv[1] = *(const float4*)&s_wk[(c+1)*COUT + ocg];
            *(float4*)wv[2] = *(const float4*)&s_wk[(c+2)*COUT + ocg];
            *(float4*)wv[3] = *(const float4*)&s_wk[(c+3)*COUT + ocg];
#pragma unroll
            for (int i = 0; i < 4; i++) {
                float sv[4];
                *(float4*)sv = *(const float4*)&s_s[(pgb+i)*68 + c];
#pragma unroll
                for (int j = 0; j < 4; j++)
                    acc[i][j] += sv[0]*wv[0][j] + sv[1]*wv[1][j]
                               + sv[2]*wv[2][j] + sv[3]*wv[3][j];
            }
        }
    }

    __syncthreads();   // all GEMM reads of s_s/s_idx/s_w complete

    // epilogue: bias, partial BN sums, smem transpose
    float* s_out  = s_s;                 // [64 oc][67]
    float* s_red  = (float*)s_idx;       // [16 grp][64 oc]
    float* s_red2 = s_w;                 // [16 grp][64 oc]
    int grp = tid >> 4;
    {
        float bo[4];
        *(float4*)bo = *(const float4*)&bias[ocg];
        float psum[4] = {0,0,0,0}, pqq[4] = {0,0,0,0};
#pragma unroll
        for (int i = 0; i < 4; i++)
#pragma unroll
            for (int j = 0; j < 4; j++) {
                float y = acc[i][j] + bo[j];
                s_out[(ocg+j)*67 + pgb + i] = y;
                psum[j] += y;
                pqq[j]  += y*y;
            }
#pragma unroll
        for (int j = 0; j < 4; j++) {
            s_red [grp*64 + ocg + j] = psum[j];
            s_red2[grp*64 + ocg + j] = pqq[j];
        }
    }
    __syncthreads();

    if (tid < 64) {
        float t = 0.f;
#pragma unroll
        for (int g = 0; g < 16; g++) t += s_red[g*64 + tid];
        atomicAdd(&g_sum[tid], t);
    } else if (tid < 128) {
        int c = tid - 64;
        float t = 0.f;
#pragma unroll
        for (int g = 0; g < 16; g++) t += s_red2[g*64 + c];
        atomicAdd(&g_sumsq[c], t);
    }

    // coalesced writeout: 4 px per thread-iter via float4 STG
    for (int i = tid; i < COUT*16; i += 256) {
        int o = i >> 4, p4 = (i & 15) * 4;
        float4 v;
        v.x = s_out[o*67 + p4 + 0];
        v.y = s_out[o*67 + p4 + 1];
        v.z = s_out[o*67 + p4 + 2];
        v.w = s_out[o*67 + p4 + 3];
        *(float4*)&g_y[((size_t)b*COUT + o)*HW + h*WW + w0 + p4] = v;
    }
}

// ---------------- kernel D: batchnorm + relu ----------------
__global__ __launch_bounds__(256) void k_bn(
    const float* __restrict__ gamma, const float* __restrict__ beta,
    float* __restrict__ out)
{
    int i4 = blockIdx.x * 256 + threadIdx.x;
    if (i4 >= BB*COUT*HW/4) return;
    int c = (i4 >> 12) & 63;
    const float N = (float)(BB*HW);
    float mean = g_sum[c] / N;
    float var  = g_sumsq[c]/N - mean*mean;
    float inv  = rsqrtf(var + 1e-5f);
    float sc   = gamma[c]*inv;
    float sh   = beta[c] - mean*sc;
    float4 v = ((const float4*)g_y)[i4];
    float4 r;
    r.x = fmaxf(v.x*sc + sh, 0.f);
    r.y = fmaxf(v.y*sc + sh, 0.f);
    r.z = fmaxf(v.z*sc + sh, 0.f);
    r.w = fmaxf(v.w*sc + sh, 0.f);
    ((float4*)out)[i4] = r;
}

// ---------------- launch ----------------
extern "C" void kernel_launch(void* const* d_in, const int* in_sizes, int n_in,
                              void* d_out, int out_size)
{
    const float* x     = (const float*)d_in[0];
    const float* ow    = (const float*)d_in[1];
    const float* ob    = (const float*)d_in[2];
    const float* mw    = (const float*)d_in[3];
    const float* mb    = (const float*)d_in[4];
    const float* w     = (const float*)d_in[5];
    const float* bias  = (const float*)d_in[6];
    const float* gamma = (const float*)d_in[7];
    const float* beta  = (const float*)d_in[8];

    const int smemA = 27*CIN*12*4;                       // 82944 B
    const int smemB = (4096 + 64*68 + 9*64*4*2) * 4;     // 52224 B
    static int inited = 0;
    if (!inited) {
        cudaFuncSetAttribute(k_offmask, cudaFuncAttributeMaxDynamicSharedMemorySize, smemA);
        cudaFuncSetAttribute(k_deform,  cudaFuncAttributeMaxDynamicSharedMemorySize, smemB);
        inited = 1;
    }

    k_transpose<<<(KK*CIN*COUT + 255)/256, 256>>>(w);
    k_offmask<<<BB*HH/4, 256, smemA>>>(x, ow, ob, mw, mb);
    dim3 gb(WW/64, HH, BB);
    k_deform<<<gb, 256, smemB>>>(x, bias);
    k_bn<<<(BB*COUT*HW/4 + 255)/256, 256>>>(gamma, beta, (float*)d_out);
}

// round 6
// speedup vs baseline: 2.0861x; 1.5336x over previous
#include <cuda_runtime.h>
#include <cuda_bf16.h>
#include <stdint.h>
#include <math.h>

#define BB   8
#define CIN  64
#define COUT 64
#define HH   128
#define WW   128
#define KK   9
#define HW   (HH*WW)

// ---------------- scratch (device globals; no allocations) ----------------
__device__ float g_off [BB*18*HW];
__device__ float g_mask[BB*9*HW];
__device__ float g_y   [BB*COUT*HW];
__device__ __nv_bfloat16 g_wh[KK*COUT*CIN];   // split weights hi: [k][oc][c]
__device__ __nv_bfloat16 g_wl[KK*COUT*CIN];   // split weights lo
__device__ float g_sum [COUT];
__device__ float g_sumsq[COUT];

// ================= helpers =================
__device__ __forceinline__ uint32_t smem_u32(const void* p) {
    uint32_t a;
    asm("{ .reg .u64 t; cvta.to.shared.u64 t, %1; cvt.u32.u64 %0, t; }" : "=r"(a) : "l"(p));
    return a;
}
__device__ __forceinline__ uint32_t sw128(uint32_t off) { return off ^ ((off >> 3) & 0x70); }

__device__ __forceinline__ void ldsm4(uint32_t* r, uint32_t addr) {
    asm volatile("ldmatrix.sync.aligned.m8n8.x4.shared.b16 {%0,%1,%2,%3}, [%4];"
                 : "=r"(r[0]), "=r"(r[1]), "=r"(r[2]), "=r"(r[3]) : "r"(addr));
}
__device__ __forceinline__ void mma16816(float* d, const uint32_t* a, uint32_t b0, uint32_t b1) {
    asm volatile(
        "mma.sync.aligned.m16n8k16.row.col.f32.bf16.bf16.f32 "
        "{%0,%1,%2,%3}, {%4,%5,%6,%7}, {%8,%9}, {%0,%1,%2,%3};"
        : "+f"(d[0]), "+f"(d[1]), "+f"(d[2]), "+f"(d[3])
        : "r"(a[0]), "r"(a[1]), "r"(a[2]), "r"(a[3]), "r"(b0), "r"(b1));
}

// ---------------- kernel T: split weights to bf16 hi/lo + zero BN accumulators ----------------
__global__ void k_transpose(const float* __restrict__ w) {
    int i = blockIdx.x * 256 + threadIdx.x;
    if (blockIdx.x == 0 && threadIdx.x < 2*COUT) {
        if (threadIdx.x < COUT) g_sum[threadIdx.x] = 0.f;
        else                    g_sumsq[threadIdx.x - COUT] = 0.f;
    }
    if (i >= KK*COUT*CIN) return;
    int c  = i & 63;
    int oc = (i >> 6) & 63;
    int k  = i >> 12;
    float v = w[(oc*CIN + c)*KK + k];
    __nv_bfloat16 hi = __float2bfloat16(v);
    float lo = v - __bfloat162float(hi);
    g_wh[(k*COUT + oc)*CIN + c] = hi;
    g_wl[(k*COUT + oc)*CIN + c] = __float2bfloat16(lo);
}

// ---------------- kernel A: offset(18) + mask(9) 3x3 conv ----------------
__global__ __launch_bounds__(256) void k_offmask(
    const float* __restrict__ x,
    const float* __restrict__ ow, const float* __restrict__ ob,
    const float* __restrict__ mw, const float* __restrict__ mb)
{
    extern __shared__ float wsh[];   // [27][64][12]
    int tid = threadIdx.x;
    for (int i = tid; i < 27*CIN*KK; i += 256) {
        int j  = i % KK;
        int c  = (i / KK) % CIN;
        int oc = i / (KK*CIN);
        float v = (oc < 18) ? ow[(oc*CIN + c)*KK + j]
                            : mw[((oc-18)*CIN + c)*KK + j];
        wsh[(oc*CIN + c)*12 + j] = v;
    }
    __syncthreads();

    int b     = blockIdx.x / (HH/4);
    int hbase = (blockIdx.x % (HH/4)) * 4;
    int h0    = hbase + (tid >> 7) * 2;
    int wc    = tid & 127;

    float acc[2][27];
#pragma unroll
    for (int o = 0; o < 18; o++) { float v = ob[o]; acc[0][o] = v; acc[1][o] = v; }
#pragma unroll
    for (int o = 0; o < 9;  o++) { float v = mb[o]; acc[0][18+o] = v; acc[1][18+o] = v; }

    const float* xb = x + (size_t)(b*CIN)*HW + h0*WW + wc;
    bool wl = (wc > 0), wr = (wc < WW-1);
    bool rv0 = (h0 > 0), rv3 = (h0 + 2 < HH);

    for (int c = 0; c < CIN; c++) {
        const float* xc = xb + c*HW;
        float xa[4][3];
        xa[0][0] = (rv0 && wl) ? xc[-WW-1] : 0.f;
        xa[0][1] =  rv0        ? xc[-WW  ] : 0.f;
        xa[0][2] = (rv0 && wr) ? xc[-WW+1] : 0.f;
        xa[1][0] =  wl ? xc[-1] : 0.f;
        xa[1][1] =       xc[0];
        xa[1][2] =  wr ? xc[ 1] : 0.f;
        xa[2][0] =  wl ? xc[WW-1] : 0.f;
        xa[2][1] =       xc[WW  ];
        xa[2][2] =  wr ? xc[WW+1] : 0.f;
        xa[3][0] = (rv3 && wl) ? xc[2*WW-1] : 0.f;
        xa[3][1] =  rv3        ? xc[2*WW  ] : 0.f;
        xa[3][2] = (rv3 && wr) ? xc[2*WW+1] : 0.f;

#pragma unroll
        for (int o = 0; o < 27; o++) {
            const float4* wp = (const float4*)&wsh[(o*CIN + c)*12];
            float4 wA = wp[0];
            float4 wB = wp[1];
            float  w8 = wsh[(o*CIN + c)*12 + 8];
            acc[0][o] += xa[0][0]*wA.x + xa[0][1]*wA.y + xa[0][2]*wA.z
                       + xa[1][0]*wA.w + xa[1][1]*wB.x + xa[1][2]*wB.y
                       + xa[2][0]*wB.z + xa[2][1]*wB.w + xa[2][2]*w8;
            acc[1][o] += xa[1][0]*wA.x + xa[1][1]*wA.y + xa[1][2]*wA.z
                       + xa[2][0]*wA.w + xa[2][1]*wB.x + xa[2][2]*wB.y
                       + xa[3][0]*wB.z + xa[3][1]*wB.w + xa[3][2]*w8;
        }
    }

#pragma unroll
    for (int r = 0; r < 2; r++) {
        int pix = (h0 + r)*WW + wc;
#pragma unroll
        for (int o = 0; o < 18; o++)
            g_off[(b*18 + o)*HW + pix] = acc[r][o];
#pragma unroll
        for (int o = 0; o < 9; o++)
            g_mask[(b*9 + o)*HW + pix] = 2.0f / (1.0f + __expf(-acc[r][18+o]));
    }
}

// ---------------- kernel B: deformable conv via mma.sync (split bf16, 3 passes) ----------------
// Block = one (b, h): M=128 px x N=64 oc, K=9x64. 8 warps, warp tile 32x32.
// Smem (49152 B): A_hi[128][64]bf16 @0, A_lo @16384, B_hi[64][64]bf16 @32768, B_lo @40960.
// Epilogue reuses [0,32768) as out[64 oc][128 px] f32.
#define OFF_AH 0
#define OFF_AL 16384
#define OFF_BH 32768
#define OFF_BL 40960
#define SMEMB_TOTAL 49152

__global__ __launch_bounds__(256, 2) void k_deform_mma(
    const float* __restrict__ x, const float* __restrict__ bias)
{
    extern __shared__ char sm[];
    uint32_t sbase = smem_u32(sm);
    int tid = threadIdx.x, wid = tid >> 5, lane = tid & 31;
    int h = blockIdx.x, b = blockIdx.y;

    // mma warp tiling: wm = pixel tile (4 x 32), wn = oc tile (2 x 32)
    int wm = wid & 3, wn = wid >> 2;

    // ldmatrix lane addressing: row = lane&15, colbyte = (lane>>4)*16
    int lrow = lane & 15;
    uint32_t lcol = (uint32_t)(lane >> 4) * 16;
    // un-swizzled row bases + row-derived XOR values (compose with XOR, not add!)
    uint32_t arow[2], axor[2], brow[2], bxor[2];
#pragma unroll
    for (int i = 0; i < 2; i++) {
        arow[i] = (uint32_t)(wm*32 + i*16 + lrow) * 128;
        axor[i] = (arow[i] >> 3) & 0x70;
        brow[i] = (uint32_t)(wn*32 + i*16 + lrow) * 128;
        bxor[i] = (brow[i] >> 3) & 0x70;
    }

    // sampling mapping: p = pixel, cb = channel base (32 channels per thread)
    int p  = (wid & 3) * 32 + lane;
    int cb = (wid >> 2) * 32;
    const float* xb = x + (size_t)b*CIN*HW;

    float acc[2][4][4];   // [m16 tile][n8 tile][frag]
#pragma unroll
    for (int i = 0; i < 2; i++)
#pragma unroll
        for (int j = 0; j < 4; j++)
#pragma unroll
            for (int q = 0; q < 4; q++) acc[i][j][q] = 0.f;

#pragma unroll 1
    for (int k = 0; k < KK; k++) {
        __syncthreads();   // previous tap's ldmatrix reads complete

        // ---- stage split weights for this tap (8 KB hi + 8 KB lo) ----
        {
            const uint4* sh = (const uint4*)(g_wh + k*COUT*CIN);
            const uint4* sl = (const uint4*)(g_wl + k*COUT*CIN);
#pragma unroll
            for (int it = 0; it < 2; it++) {
                int i = tid + it*256;
                uint32_t sw = sw128((uint32_t)(i*16));
                *(uint4*)(sm + OFF_BH + sw) = sh[i];
                *(uint4*)(sm + OFF_BL + sw) = sl[i];
            }
        }

        // ---- bilinear sample 32 channels for this thread's pixel ----
        float dyv = g_off[((b*18 + 2*k  )*HH + h)*WW + p];
        float dxv = g_off[((b*18 + 2*k+1)*HH + h)*WW + p];
        float mv  = g_mask[((b*9 + k)*HH + h)*WW + p];
        float py = dyv + (float)(k/3 - 1) + (float)h;
        float px = dxv + (float)(k%3 - 1) + (float)p;
        float y0f = floorf(py), x0f = floorf(px);
        float ly = py - y0f, lx = px - x0f;
        int y0 = (int)y0f, x0i = (int)x0f;
        int y1 = y0 + 1,   x1 = x0i + 1;
        bool vy0 = (y0  >= 0) & (y0  < HH), vy1 = (y1 >= 0) & (y1 < HH);
        bool vx0 = (x0i >= 0) & (x0i < WW), vx1 = (x1 >= 0) & (x1 < WW);
        int yc0 = min(max(y0 , 0), HH-1), yc1 = min(max(y1, 0), HH-1);
        int xc0 = min(max(x0i, 0), WW-1), xc1 = min(max(x1, 0), WW-1);
        int i00 = yc0*WW + xc0, i01 = yc0*WW + xc1;
        int i10 = yc1*WW + xc0, i11 = yc1*WW + xc1;
        float W00 = (vy0 && vx0) ? (1.f-ly)*(1.f-lx)*mv : 0.f;
        float W01 = (vy0 && vx1) ? (1.f-ly)*lx*mv       : 0.f;
        float W10 = (vy1 && vx0) ? ly*(1.f-lx)*mv       : 0.f;
        float W11 = (vy1 && vx1) ? ly*lx*mv             : 0.f;

#pragma unroll
        for (int c8 = 0; c8 < 4; c8++) {
            int c0 = cb + c8*8;
            uint32_t h4[4], l4[4];
#pragma unroll
            for (int j = 0; j < 4; j++) {
                const float* xc0p = xb + (size_t)(c0 + 2*j    )*HW;
                const float* xc1p = xb + (size_t)(c0 + 2*j + 1)*HW;
                float v0 = xc0p[i00]*W00 + xc0p[i01]*W01 + xc0p[i10]*W10 + xc0p[i11]*W11;
                float v1 = xc1p[i00]*W00 + xc1p[i01]*W01 + xc1p[i10]*W10 + xc1p[i11]*W11;
                __nv_bfloat162 hh = __floats2bfloat162_rn(v0, v1);
                float r0 = v0 - __low2float(hh);
                float r1 = v1 - __high2float(hh);
                __nv_bfloat162 ll = __floats2bfloat162_rn(r0, r1);
                h4[j] = *reinterpret_cast<uint32_t*>(&hh);
                l4[j] = *reinterpret_cast<uint32_t*>(&ll);
            }
            uint32_t sw = sw128((uint32_t)(p*128 + c0*2));
            *(uint4*)(sm + OFF_AH + sw) = *(uint4*)h4;
            *(uint4*)(sm + OFF_AL + sw) = *(uint4*)l4;
        }

        __syncthreads();

        // ---- mma: 4 k16 steps, 3 passes (ah*bh, al*bh, ah*bl) ----
#pragma unroll
        for (int kk = 0; kk < 4; kk++) {
            uint32_t kb = (uint32_t)kk * 32;
            uint32_t aoff[2], boff[2];
#pragma unroll
            for (int i = 0; i < 2; i++) {
                aoff[i] = (arow[i] + lcol + kb) ^ axor[i];   // disjoint bits, then XOR
                boff[i] = (brow[i] + lcol + kb) ^ bxor[i];
            }
            uint32_t ah[2][4], bh[2][4];
            ldsm4(ah[0], sbase + OFF_AH + aoff[0]);
            ldsm4(ah[1], sbase + OFF_AH + aoff[1]);
            ldsm4(bh[0], sbase + OFF_BH + boff[0]);
            ldsm4(bh[1], sbase + OFF_BH + boff[1]);
            // pass 1: ah * bh
#pragma unroll
            for (int i = 0; i < 2; i++) {
                mma16816(acc[i][0], ah[i], bh[0][0], bh[0][2]);
                mma16816(acc[i][1], ah[i], bh[0][1], bh[0][3]);
                mma16816(acc[i][2], ah[i], bh[1][0], bh[1][2]);
                mma16816(acc[i][3], ah[i], bh[1][1], bh[1][3]);
            }
            // pass 2: al * bh
            uint32_t al[2][4];
            ldsm4(al[0], sbase + OFF_AL + aoff[0]);
            ldsm4(al[1], sbase + OFF_AL + aoff[1]);
#pragma unroll
            for (int i = 0; i < 2; i++) {
                mma16816(acc[i][0], al[i], bh[0][0], bh[0][2]);
                mma16816(acc[i][1], al[i], bh[0][1], bh[0][3]);
                mma16816(acc[i][2], al[i], bh[1][0], bh[1][2]);
                mma16816(acc[i][3], al[i], bh[1][1], bh[1][3]);
            }
            // pass 3: ah * bl
            uint32_t bl[2][4];
            ldsm4(bl[0], sbase + OFF_BL + boff[0]);
            ldsm4(bl[1], sbase + OFF_BL + boff[1]);
#pragma unroll
            for (int i = 0; i < 2; i++) {
                mma16816(acc[i][0], ah[i], bl[0][0], bl[0][2]);
                mma16816(acc[i][1], ah[i], bl[0][1], bl[0][3]);
                mma16816(acc[i][2], ah[i], bl[1][0], bl[1][2]);
                mma16816(acc[i][3], ah[i], bl[1][1], bl[1][3]);
            }
        }
    }

    // ---- epilogue: acc -> smem transpose [oc][pix] -> coalesced STG ----
    __syncthreads();
    float* s_out = (float*)sm;   // [64][128]
    {
        int r0 = lane >> 2, c0 = (lane & 3) * 2;
#pragma unroll
        for (int i = 0; i < 2; i++) {
#pragma unroll
            for (int j = 0; j < 4; j++) {
                int pix = wm*32 + i*16 + r0;
                int oc  = wn*32 + j*8 + c0;
                s_out[(oc  )*128 + pix    ] = acc[i][j][0];
                s_out[(oc+1)*128 + pix    ] = acc[i][j][1];
                s_out[(oc  )*128 + pix + 8] = acc[i][j][2];
                s_out[(oc+1)*128 + pix + 8] = acc[i][j][3];
            }
        }
    }
    __syncthreads();
    for (int i = tid; i < COUT*32; i += 256) {
        int o = i >> 5, p4 = (i & 31) * 4;
        float bo = __ldg(&bias[o]);
        float4 v = *(float4*)&s_out[o*128 + p4];
        v.x += bo; v.y += bo; v.z += bo; v.w += bo;
        *(float4*)&g_y[((size_t)b*COUT + o)*HW + h*WW + p4] = v;
    }
}

// ---------------- kernel C: per-channel sum / sumsq ----------------
__global__ __launch_bounds__(256) void k_reduce() {
    int plane = blockIdx.x;
    int c = plane & 63;
    const float4* yp = (const float4*)(g_y + (size_t)plane * HW);
    float s = 0.f, sq = 0.f;
    for (int i = threadIdx.x; i < HW/4; i += 256) {
        float4 v = yp[i];
        s  += v.x + v.y + v.z + v.w;
        sq += v.x*v.x + v.y*v.y + v.z*v.z + v.w*v.w;
    }
#pragma unroll
    for (int o = 16; o > 0; o >>= 1) {
        s  += __shfl_down_sync(0xffffffffu, s,  o);
        sq += __shfl_down_sync(0xffffffffu, sq, o);
    }
    __shared__ float ss[8], ssq[8];
    if ((threadIdx.x & 31) == 0) { ss[threadIdx.x>>5] = s; ssq[threadIdx.x>>5] = sq; }
    __syncthreads();
    if (threadIdx.x == 0) {
        float t = 0.f, tq = 0.f;
#pragma unroll
        for (int i = 0; i < 8; i++) { t += ss[i]; tq += ssq[i]; }
        atomicAdd(&g_sum[c], t);
        atomicAdd(&g_sumsq[c], tq);
    }
}

// ---------------- kernel D: batchnorm + relu ----------------
__global__ __launch_bounds__(256) void k_bn(
    const float* __restrict__ gamma, const float* __restrict__ beta,
    float* __restrict__ out)
{
    int i4 = blockIdx.x * 256 + threadIdx.x;
    if (i4 >= BB*COUT*HW/4) return;
    int c = (i4 >> 12) & 63;
    const float N = (float)(BB*HW);
    float mean = g_sum[c] / N;
    float var  = g_sumsq[c]/N - mean*mean;
    float inv  = rsqrtf(var + 1e-5f);
    float sc   = gamma[c]*inv;
    float sh   = beta[c] - mean*sc;
    float4 v = ((const float4*)g_y)[i4];
    float4 r;
    r.x = fmaxf(v.x*sc + sh, 0.f);
    r.y = fmaxf(v.y*sc + sh, 0.f);
    r.z = fmaxf(v.z*sc + sh, 0.f);
    r.w = fmaxf(v.w*sc + sh, 0.f);
    ((float4*)out)[i4] = r;
}

// ---------------- launch ----------------
extern "C" void kernel_launch(void* const* d_in, const int* in_sizes, int n_in,
                              void* d_out, int out_size)
{
    const float* x     = (const float*)d_in[0];
    const float* ow    = (const float*)d_in[1];
    const float* ob    = (const float*)d_in[2];
    const float* mw    = (const float*)d_in[3];
    const float* mb    = (const float*)d_in[4];
    const float* w     = (const float*)d_in[5];
    const float* bias  = (const float*)d_in[6];
    const float* gamma = (const float*)d_in[7];
    const float* beta  = (const float*)d_in[8];

    const int smemA = 27*CIN*12*4;   // 82944 B
    static int inited = 0;
    if (!inited) {
        cudaFuncSetAttribute(k_offmask,    cudaFuncAttributeMaxDynamicSharedMemorySize, smemA);
        cudaFuncSetAttribute(k_deform_mma, cudaFuncAttributeMaxDynamicSharedMemorySize, SMEMB_TOTAL);
        inited = 1;
    }

    k_transpose<<<(KK*COUT*CIN + 255)/256, 256>>>(w);
    k_offmask<<<BB*HH/4, 256, smemA>>>(x, ow, ob, mw, mb);
    dim3 gb(HH, BB);
    k_deform_mma<<<gb, 256, SMEMB_TOTAL>>>(x, bias);
    k_reduce<<<BB*COUT, 256>>>();
    k_bn<<<(BB*COUT*HW/4 + 255)/256, 256>>>(gamma, beta, (float*)d_out);
}